// round 7
// baseline (speedup 1.0000x reference)
#include <cuda_runtime.h>

#define TINYV 1.1920929e-7f        // float32 machine eps = np.finfo(float32).eps
#define CGRID 0.49951171875f       // 0.5 - 2^-11, exact in fp32

// Literal custom_round: floor((x - copysign(TINY,x)) + 0.5). Replicates reference
// bit-for-bit at ALL magnitudes (incl. |x|>=2 half-ties where the TINY is absorbed
// by RNE and the reference effectively rounds half-up).
__device__ __forceinline__ float cround_exact(float x) {
    return floorf((x - copysignf(TINYV, x)) + 0.5f);
}
// Grid custom_round: trunc(x + copysign(0.5-2^-11, x)) == cround ONLY for |x| < 2
// on a coarse (>=1/8) grid (half-ties round toward zero there, matching the
// reference's effective behavior below 2). Used ONLY on the decode path where
// inputs are provably in [-1.25, 1.875].
__device__ __forceinline__ float cround_grid(float x) {
    return truncf(x + copysignf(CGRID, x));
}

// first-occurrence argmax scan: sel[j] = (|e_j|==m) first time; step = sign(e_k),
// with the all-zero (m==0) fallback step = copysign(1, -xa0) (== reference rule).
__device__ __forceinline__ void scanfn(const float e[8], float m, float xa0,
                                       bool sel[8], float& step) {
    bool seen = false;
#pragma unroll
    for (int j = 0; j < 8; j++) {
        bool eq = (fabsf(e[j]) == m);
        sel[j] = eq && !seen;
        seen = seen || eq;
    }
    float t = e[0];
#pragma unroll
    for (int j = 1; j < 8; j++) t = sel[j] ? e[j] : t;
    t = (m == 0.0f) ? -xa0 : t;
    step = copysignf(1.0f, t);
}

// ---------- closed-form variant: ONLY for inputs on a dyadic grid ----------
// d = sum e^2 (+ 1 - 2*max|e| if odd branch). On grid inputs every term and
// partial sum is an exact dyadic -> bit-equal to the reference's sequential sum.
// GRIDROUND selects the cheap cround (decode only, |x|<2 proven).
template<bool GRIDROUND>
__device__ __forceinline__ void cp_e8_closed(const float x[8], float y[8]) {
    float fA[8], eA[8], fB[8], eB[8];
    float xs0;
#pragma unroll
    for (int j = 0; j < 8; j++) {
        fA[j] = GRIDROUND ? cround_grid(x[j]) : cround_exact(x[j]);
        eA[j] = x[j] - fA[j];
        float xs = x[j] - 0.5f;
        if (j == 0) xs0 = xs;
        fB[j] = GRIDROUND ? cround_grid(xs) : cround_exact(xs);
        eB[j] = xs - fB[j];
    }

    float sA = ((fA[0]+fA[1])+(fA[2]+fA[3])) + ((fA[4]+fA[5])+(fA[6]+fA[7]));
    float sB = ((fB[0]+fB[1])+(fB[2]+fB[3])) + ((fB[4]+fB[5])+(fB[6]+fB[7]));
    bool oddA = (((int)sA) & 1) != 0;
    bool oddB = (((int)sB) & 1) != 0;

    float mA = fmaxf(fmaxf(fmaxf(fabsf(eA[0]),fabsf(eA[1])),fmaxf(fabsf(eA[2]),fabsf(eA[3]))),
                     fmaxf(fmaxf(fabsf(eA[4]),fabsf(eA[5])),fmaxf(fabsf(eA[6]),fabsf(eA[7]))));
    float mB = fmaxf(fmaxf(fmaxf(fabsf(eB[0]),fabsf(eB[1])),fmaxf(fabsf(eB[2]),fabsf(eB[3]))),
                     fmaxf(fmaxf(fabsf(eB[4]),fabsf(eB[5])),fmaxf(fabsf(eB[6]),fabsf(eB[7]))));

    bool selA[8], selB[8];
    float stepA, stepB;
    scanfn(eA, mA, x[0], selA, stepA);
    scanfn(eB, mB, xs0,  selB, stepB);

    float dA = eA[0]*eA[0];
#pragma unroll
    for (int j = 1; j < 8; j++) dA = fmaf(eA[j], eA[j], dA);
    dA = oddA ? (dA + fmaf(-2.0f, mA, 1.0f)) : dA;   // (e_k-sign(e_k))^2 correction

    float dB = eB[0]*eB[0];
#pragma unroll
    for (int j = 1; j < 8; j++) dB = fmaf(eB[j], eB[j], dB);
    dB = oddB ? (dB + fmaf(-2.0f, mB, 1.0f)) : dB;

    bool pickA = dA < dB;    // tie -> B, matching jnp.where(d0 < d1, y0, y1)

    float h   = pickA ? 0.0f : 0.5f;
    float st  = pickA ? stepA : stepB;
    bool oddc = pickA ? oddA : oddB;
#pragma unroll
    for (int j = 0; j < 8; j++) {
        float base = (pickA ? fA[j] : fB[j]) + h;
        bool flip = oddc && (pickA ? selA[j] : selB[j]);
        y[j] = flip ? (base + st) : base;
    }
}

// ---------- full-replication variant: for the continuous layer-0 input ----------
__device__ __forceinline__ float e8_branch_full(const float xa[8], const float xo[8],
                                                float half, float yc[8]) {
    float f[8], e[8];
#pragma unroll
    for (int j = 0; j < 8; j++) { f[j] = cround_exact(xa[j]); e[j] = xa[j] - f[j]; }
    float sum = ((f[0]+f[1])+(f[2]+f[3])) + ((f[4]+f[5])+(f[6]+f[7]));
    bool odd = (((int)sum) & 1) != 0;
    float m = fmaxf(fmaxf(fmaxf(fabsf(e[0]),fabsf(e[1])),fmaxf(fabsf(e[2]),fabsf(e[3]))),
                    fmaxf(fmaxf(fabsf(e[4]),fabsf(e[5])),fmaxf(fabsf(e[6]),fabsf(e[7]))));
    bool sel[8]; float step;
    scanfn(e, m, xa[0], sel, step);
#pragma unroll
    for (int j = 0; j < 8; j++) {
        float base = f[j] + half;
        yc[j] = (odd && sel[j]) ? (base + step) : base;
    }
    float r = xo[0] - yc[0];
    float d = r * r;
#pragma unroll
    for (int j = 1; j < 8; j++) { r = xo[j] - yc[j]; d = fmaf(r, r, d); }
    return d;
}

__device__ __forceinline__ void cp_e8_full(const float x[8], float y[8]) {
    float yA[8], yB[8], xs[8];
    float dA = e8_branch_full(x, x, 0.0f, yA);
#pragma unroll
    for (int j = 0; j < 8; j++) xs[j] = x[j] - 0.5f;
    float dB = e8_branch_full(xs, x, 0.5f, yB);
    bool pickA = dA < dB;
#pragma unroll
    for (int j = 0; j < 8; j++) y[j] = pickA ? yA[j] : yB[j];
}

__global__ __launch_bounds__(128)
void LatticeQuantizer_kernel(const float* __restrict__ x,
                             const float* __restrict__ beta_p,
                             const float* __restrict__ eps,
                             float* __restrict__ out, int N)
{
    int i = blockIdx.x * blockDim.x + threadIdx.x;
    if (i >= N) return;

    float beta = __ldg(beta_p);
    float4 e0 = __ldg((const float4*)eps);
    float4 e1 = __ldg((const float4*)eps + 1);
    float ev[8] = {e0.x, e0.y, e0.z, e0.w, e1.x, e1.y, e1.z, e1.w};

    float4 va = ((const float4*)x)[2 * i];
    float4 vb = ((const float4*)x)[2 * i + 1];
    float xl[8] = {va.x, va.y, va.z, va.w, vb.x, vb.y, vb.z, vb.w};
#pragma unroll
    for (int j = 0; j < 8; j++) xl[j] = __fdiv_rn(xl[j], beta);  // IEEE div under fast_math

    float xh[8];

#pragma unroll
    for (int m = 0; m < 3; m++) {
        // ---- encode: yq = closest_point_E8(xl + eps) ----
        float xe[8], yq[8];
#pragma unroll
        for (int j = 0; j < 8; j++) xe[j] = xl[j] + ev[j];
        if (m == 0) cp_e8_full(xe, yq);            // continuous input: bit-exact path
        else        cp_e8_closed<false>(xe, yq);   // 1/8-grid input: closed-form dist,
                                                   // exact cround (|xe| can exceed 2)

        // ---- acc = yq @ G_inv via exact forward substitution (acc @ Gm = yq) ----
        float a[8];
        a[0] = 0.5f * yq[0];
#pragma unroll
        for (int j = 1; j < 7; j++) a[j] = a[j - 1] + yq[j];
        float s06 = ((a[0] + a[1]) + (a[2] + a[3])) + ((a[4] + a[5]) + a[6]);
        a[7] = fmaf(2.0f, yq[7], -s06);

        // ---- b = custom_round(fmod(acc, 4)): r quarter-integer in (-4,4),
        //      ties at +-2.5/+-3.5 -> MUST use exact cround ----
        float bv[8];
#pragma unroll
        for (int j = 0; j < 8; j++) {
            float r = fmaf(-4.0f, truncf(a[j] * 0.25f), a[j]);  // == fmodf(a,4) exactly
            bv[j] = cround_exact(r);
        }

        // ---- next layer input ----
#pragma unroll
        for (int j = 0; j < 8; j++) xl[j] = yq[j] * 0.25f;

        // ---- Gb = b @ G.T, sparse exact form ----
        float gb[8];
        {
            float h = 0.5f * bv[7];
            gb[0] = fmaf(2.0f, bv[0], -bv[1]) + h;
#pragma unroll
            for (int j = 1; j < 6; j++) gb[j] = (bv[j] - bv[j + 1]) + h;
            gb[6] = bv[6] + h;
            gb[7] = h;
        }

        // ---- x_i = Gb - 4*closest_point_E8(Gb/4);  xh += 4^m * x_i ----
        // gq in [-0.75, 1.875], xs in [-1.25, 1.375]: |.| < 2 -> grid cround safe.
        float gq[8], cpv[8];
#pragma unroll
        for (int j = 0; j < 8; j++) gq[j] = gb[j] * 0.25f;
        cp_e8_closed<true>(gq, cpv);

        float sc = (m == 0) ? 1.0f : (m == 1 ? 4.0f : 16.0f);
#pragma unroll
        for (int j = 0; j < 8; j++) {
            float xi = fmaf(-4.0f, cpv[j], gb[j]);   // exact dyadic
            if (m == 0) xh[j] = xi;
            else        xh[j] = fmaf(sc, xi, xh[j]); // exact accumulation
        }
    }

    float4 o0, o1;
    o0.x = beta * xh[0]; o0.y = beta * xh[1]; o0.z = beta * xh[2]; o0.w = beta * xh[3];
    o1.x = beta * xh[4]; o1.y = beta * xh[5]; o1.z = beta * xh[6]; o1.w = beta * xh[7];
    ((float4*)out)[2 * i]     = o0;
    ((float4*)out)[2 * i + 1] = o1;
}

extern "C" void kernel_launch(void* const* d_in, const int* in_sizes, int n_in,
                              void* d_out, int out_size) {
    const float* x    = (const float*)d_in[0];
    const float* beta = (const float*)d_in[1];
    const float* eps  = (const float*)d_in[4];
    float* out = (float*)d_out;

    int N = in_sizes[0] / 8;
    int threads = 128;
    int blocks = (N + threads - 1) / threads;
    LatticeQuantizer_kernel<<<blocks, threads>>>(x, beta, eps, out, N);
}

// round 8
// speedup vs baseline: 1.1290x; 1.1290x over previous
#include <cuda_runtime.h>

#define TINYV 1.1920929e-7f        // float32 machine eps = np.finfo(float32).eps
#define CGRID 0.49951171875f       // 0.5 - 2^-11, exact in fp32

typedef unsigned long long u64;

// ---- packed f32x2 helpers (sm_103a). Per-lane IEEE RN: bit-identical to scalar. ----
__device__ __forceinline__ u64 pk(float lo, float hi) {
    u64 r; asm("mov.b64 %0, {%1, %2};" : "=l"(r) : "f"(lo), "f"(hi)); return r;
}
__device__ __forceinline__ void upk(u64 v, float& lo, float& hi) {
    asm("mov.b64 {%0, %1}, %2;" : "=f"(lo), "=f"(hi) : "l"(v));
}
__device__ __forceinline__ u64 add2(u64 a, u64 b) {
    u64 r; asm("add.rn.f32x2 %0, %1, %2;" : "=l"(r) : "l"(a), "l"(b)); return r;
}
__device__ __forceinline__ u64 mul2(u64 a, u64 b) {
    u64 r; asm("mul.rn.f32x2 %0, %1, %2;" : "=l"(r) : "l"(a), "l"(b)); return r;
}
__device__ __forceinline__ u64 fma2(u64 a, u64 b, u64 c) {
    u64 r; asm("fma.rn.f32x2 %0, %1, %2, %3;" : "=l"(r) : "l"(a), "l"(b), "l"(c)); return r;
}

// packed-pair constants (bit patterns of (v, v))
#define H2C  0x3F0000003F000000ULL   // (+0.5, +0.5)
#define NH2C 0xBF000000BF000000ULL   // (-0.5, -0.5)
#define M1C  0xBF800000BF800000ULL   // (-1.0, -1.0)
#define M4C  0xC0800000C0800000ULL   // (-4.0, -4.0)
#define QC   0x3E8000003E800000ULL   // (0.25, 0.25)
#define S4C  0x4080000040800000ULL   // (4.0, 4.0)
#define S16C 0x4180000041800000ULL   // (16.0, 16.0)

// -copysign(TINY, x) as a single logic op: (~sign(x)) | bits(2^-23)
__device__ __forceinline__ float negtiny(float x) {
    return __int_as_float(((__float_as_int(x) & 0x80000000) ^ 0x80000000) | 0x34000000);
}

// Literal custom_round, 8-wide with packed adds. Sequence identical to
// floor((x - copysign(TINY,x)) + 0.5) per lane (FADD(x,-s) == x-s).
__device__ __forceinline__ void cround8_exact(const float x[8], float f[8]) {
#pragma unroll
    for (int p = 0; p < 4; p++) {
        float a0 = x[2*p], a1 = x[2*p+1];
        u64 v = add2(add2(pk(a0, a1), pk(negtiny(a0), negtiny(a1))), H2C);
        float v0, v1; upk(v, v0, v1);
        f[2*p] = floorf(v0); f[2*p+1] = floorf(v1);
    }
}
// Grid custom_round (valid |x| < 2 on >=1/8 grid; validated on decode in R5):
// trunc(x + copysign(0.5-2^-11, x))
__device__ __forceinline__ void cround8_grid(const float x[8], float f[8]) {
#pragma unroll
    for (int p = 0; p < 4; p++) {
        float a0 = x[2*p], a1 = x[2*p+1];
        u64 v = add2(pk(a0, a1), pk(copysignf(CGRID, a0), copysignf(CGRID, a1)));
        float v0, v1; upk(v, v0, v1);
        f[2*p] = truncf(v0); f[2*p+1] = truncf(v1);
    }
}

// first-occurrence argmax scan (R3-proven): sel[j] = first j with |e_j|==m;
// step = sign(e_k), fallback (m==0) step = copysign(1, -xa0).
__device__ __forceinline__ void scanfn(const float e[8], float m, float xa0,
                                       bool sel[8], float& step) {
    bool seen = false;
#pragma unroll
    for (int j = 0; j < 8; j++) {
        bool eq = (fabsf(e[j]) == m);
        sel[j] = eq && !seen;
        seen = seen || eq;
    }
    float t = e[0];
#pragma unroll
    for (int j = 1; j < 8; j++) t = sel[j] ? e[j] : t;
    t = (m == 0.0f) ? -xa0 : t;
    step = copysignf(1.0f, t);
}

// One branch of closest_point_E8, full replication (R3 structure), packed math.
// GR: grid cround (decode / layer-2 encode only). SHIFTED: the D8+1/2 branch.
template<bool GR, bool SHIFTED>
__device__ __forceinline__ float e8_branch(const float xa[8], const u64 xo2[4],
                                           float yc[8]) {
    float f[8], e[8];
    if (GR) cround8_grid(xa, f); else cround8_exact(xa, f);
#pragma unroll
    for (int p = 0; p < 4; p++) {        // e = xa - f  (fma(f,-1,xa): single rounding)
        u64 e2 = fma2(pk(f[2*p], f[2*p+1]), M1C, pk(xa[2*p], xa[2*p+1]));
        upk(e2, e[2*p], e[2*p+1]);
    }

    // parity of sum(f): packed tree (exact small integers -> any order)
    u64 s = add2(add2(pk(f[0],f[1]), pk(f[2],f[3])),
                 add2(pk(f[4],f[5]), pk(f[6],f[7])));
    float sl, sh; upk(s, sl, sh);
    bool odd = (((int)(sl + sh)) & 1) != 0;

    // max |e| (FMNMX absorbs |.|)
    float m = fmaxf(fmaxf(fmaxf(fabsf(e[0]),fabsf(e[1])),fmaxf(fabsf(e[2]),fabsf(e[3]))),
                    fmaxf(fmaxf(fabsf(e[4]),fabsf(e[5])),fmaxf(fabsf(e[6]),fabsf(e[7]))));

    bool sel[8]; float step;
    scanfn(e, m, xa[0], sel, step);

    // candidate assembly (base = f (+0.5 if SHIFTED), flip one coord if odd)
#pragma unroll
    for (int p = 0; p < 4; p++) {
        float b0, b1;
        if (SHIFTED) { u64 b2 = add2(pk(f[2*p], f[2*p+1]), H2C); upk(b2, b0, b1); }
        else         { b0 = f[2*p]; b1 = f[2*p+1]; }
        yc[2*p]   = (odd && sel[2*p])   ? (b0 + step) : b0;
        yc[2*p+1] = (odd && sel[2*p+1]) ? (b1 + step) : b1;
    }

    // distance vs ORIGINAL x: packed residuals, scalar sequential sum (reference order)
    float r[8];
#pragma unroll
    for (int p = 0; p < 4; p++) {
        u64 r2 = fma2(pk(yc[2*p], yc[2*p+1]), M1C, xo2[p]);
        upk(r2, r[2*p], r[2*p+1]);
    }
    float d = r[0] * r[0];
#pragma unroll
    for (int j = 1; j < 8; j++) d = fmaf(r[j], r[j], d);
    return d;
}

template<bool GR>
__device__ __forceinline__ void cp_e8(const float x[8], float y[8]) {
    u64 x2[4];
    float xs[8];
#pragma unroll
    for (int p = 0; p < 4; p++) {
        x2[p] = pk(x[2*p], x[2*p+1]);
        u64 s2 = add2(x2[p], NH2C);            // x - 0.5, packed (== scalar)
        upk(s2, xs[2*p], xs[2*p+1]);
    }
    float yA[8], yB[8];
    float dA = e8_branch<GR, false>(x,  x2, yA);
    float dB = e8_branch<GR, true >(xs, x2, yB);
    bool pickA = dA < dB;                      // tie -> B (jnp.where(d0 < d1, y0, y1))
#pragma unroll
    for (int j = 0; j < 8; j++) y[j] = pickA ? yA[j] : yB[j];
}

__global__ __launch_bounds__(128)
void LatticeQuantizer_kernel(const float* __restrict__ x,
                             const float* __restrict__ beta_p,
                             const float* __restrict__ eps,
                             float* __restrict__ out, int N)
{
    int i = blockIdx.x * blockDim.x + threadIdx.x;
    if (i >= N) return;

    float beta = __ldg(beta_p);
    float4 ea = __ldg((const float4*)eps);
    float4 eb = __ldg((const float4*)eps + 1);
    u64 ev2[4] = { pk(ea.x, ea.y), pk(ea.z, ea.w), pk(eb.x, eb.y), pk(eb.z, eb.w) };

    float4 va = ((const float4*)x)[2 * i];
    float4 vb = ((const float4*)x)[2 * i + 1];
    float xl[8] = {va.x, va.y, va.z, va.w, vb.x, vb.y, vb.z, vb.w};
#pragma unroll
    for (int j = 0; j < 8; j++) xl[j] = __fdiv_rn(xl[j], beta);  // IEEE div under fast_math

    u64 xh2[4];

#pragma unroll
    for (int m = 0; m < 3; m++) {
        // ---- encode: yq = closest_point_E8(xl + eps) ----
        float xe[8], yq[8];
#pragma unroll
        for (int p = 0; p < 4; p++) {
            u64 t = add2(pk(xl[2*p], xl[2*p+1]), ev2[p]);
            upk(t, xe[2*p], xe[2*p+1]);
        }
        // layer 0: continuous; layer 1: grid but |xe| can exceed 2 -> exact cround.
        // layer 2: 1/8 grid with |xe| <= ~0.94 < 2 -> grid cround valid.
        if (m < 2) cp_e8<false>(xe, yq);
        else       cp_e8<true >(xe, yq);

        // ---- acc = yq @ G_inv via exact forward substitution (acc @ Gm = yq) ----
        float a[8];
        a[0] = 0.5f * yq[0];
#pragma unroll
        for (int j = 1; j < 7; j++) a[j] = a[j - 1] + yq[j];
        float s06 = ((a[0] + a[1]) + (a[2] + a[3])) + ((a[4] + a[5]) + a[6]);
        a[7] = fmaf(2.0f, yq[7], -s06);

        // ---- b = custom_round(fmod(acc,4)): quarter-int in (-4,4), ties at
        //      +-2.5/+-3.5 -> exact cround required ----
        float r8[8], bv[8];
#pragma unroll
        for (int j = 0; j < 8; j++)
            r8[j] = fmaf(-4.0f, truncf(a[j] * 0.25f), a[j]);  // == fmodf(a,4) exactly
        cround8_exact(r8, bv);

        // ---- next layer input: xl = yq * 0.25 (packed, exact) ----
#pragma unroll
        for (int p = 0; p < 4; p++) {
            u64 t = mul2(pk(yq[2*p], yq[2*p+1]), QC);
            upk(t, xl[2*p], xl[2*p+1]);
        }

        // ---- Gb = b @ G.T, sparse exact form ----
        float gb[8];
        {
            float h = 0.5f * bv[7];
            gb[0] = fmaf(2.0f, bv[0], -bv[1]) + h;
#pragma unroll
            for (int j = 1; j < 6; j++) gb[j] = (bv[j] - bv[j + 1]) + h;
            gb[6] = bv[6] + h;
            gb[7] = h;
        }

        // ---- x_i = Gb - 4*closest_point_E8(Gb/4);  xh += 4^m * x_i ----
        // gq in [-0.75, 1.875], branch-B input in [-1.25, 1.375] -> grid cround valid.
        float gq[8], cpv[8];
#pragma unroll
        for (int p = 0; p < 4; p++) {
            u64 t = mul2(pk(gb[2*p], gb[2*p+1]), QC);
            upk(t, gq[2*p], gq[2*p+1]);
        }
        cp_e8<true>(gq, cpv);

#pragma unroll
        for (int p = 0; p < 4; p++) {
            u64 xi = fma2(pk(cpv[2*p], cpv[2*p+1]), M4C, pk(gb[2*p], gb[2*p+1]));
            if (m == 0)      xh2[p] = xi;
            else if (m == 1) xh2[p] = fma2(xi, S4C,  xh2[p]);   // exact dyadics
            else             xh2[p] = fma2(xi, S16C, xh2[p]);
        }
    }

    u64 bb = pk(beta, beta);
    float o[8];
#pragma unroll
    for (int p = 0; p < 4; p++) {
        u64 t = mul2(xh2[p], bb);
        upk(t, o[2*p], o[2*p+1]);
    }
    float4 o0 = {o[0], o[1], o[2], o[3]};
    float4 o1 = {o[4], o[5], o[6], o[7]};
    ((float4*)out)[2 * i]     = o0;
    ((float4*)out)[2 * i + 1] = o1;
}

extern "C" void kernel_launch(void* const* d_in, const int* in_sizes, int n_in,
                              void* d_out, int out_size) {
    const float* x    = (const float*)d_in[0];
    const float* beta = (const float*)d_in[1];
    const float* eps  = (const float*)d_in[4];
    float* out = (float*)d_out;

    int N = in_sizes[0] / 8;
    int threads = 128;
    int blocks = (N + threads - 1) / threads;
    LatticeQuantizer_kernel<<<blocks, threads>>>(x, beta, eps, out, N);
}